// round 2
// baseline (speedup 1.0000x reference)
#include <cuda_runtime.h>
#include <cuda_bf16.h>
#include <cstdint>
#include <cstddef>

// ---------------- problem constants ----------------
#define B_ROWS 4096
#define C_ROWS 65536
#define DIM    1024
#define TOPK   5

// ---------------- GEMM tiling ----------------
#define BM 128
#define BN 128
#define BK 32
#define NTILES (C_ROWS / BN)          // 512
#define CAND_PER_TILE 8
#define CAND_PER_ROW (NTILES * CAND_PER_TILE)  // 4096
#define RESCORE 16

// padded smem row: 40 bf16 = 80 B (conflict-free ldmatrix, 16B-aligned chunks)
#define SROW 40
#define STAGE_BYTES (2 * BM * SROW * 2)        // A+B per stage = 20480
#define CS_STRIDE 129
#define SMEM_BYTES (BM * CS_STRIDE * 4)        // 66048 > 2*STAGE_BYTES

// ---------------- device scratch (sanctioned: __device__ globals) ----------------
__device__ __align__(16) __nv_bfloat16 g_memb[(size_t)C_ROWS * DIM]; // normalized bf16 memory
__device__ __align__(16) __nv_bfloat16 g_xb[(size_t)B_ROWS * DIM];   // raw bf16 x
__device__ float g_minv[C_ROWS];
__device__ float g_xinv[B_ROWS];
__device__ __align__(16) float g_cv[(size_t)B_ROWS * CAND_PER_ROW];
__device__ __align__(16) int   g_ci[(size_t)B_ROWS * CAND_PER_ROW];

// ---------------- small PTX helpers ----------------
__device__ __forceinline__ void cp16(uint32_t saddr, const void* gaddr) {
    asm volatile("cp.async.cg.shared.global [%0], [%1], 16;" :: "r"(saddr), "l"(gaddr));
}
__device__ __forceinline__ void cp_commit() { asm volatile("cp.async.commit_group;"); }
__device__ __forceinline__ void ldsm4(uint32_t (&r)[4], uint32_t addr) {
    asm volatile("ldmatrix.sync.aligned.m8n8.x4.shared.b16 {%0,%1,%2,%3}, [%4];"
                 : "=r"(r[0]), "=r"(r[1]), "=r"(r[2]), "=r"(r[3]) : "r"(addr));
}
__device__ __forceinline__ void mma16816(float (&c)[4], const uint32_t (&a)[4],
                                         uint32_t b0, uint32_t b1) {
    asm volatile(
        "mma.sync.aligned.m16n8k16.row.col.f32.bf16.bf16.f32 "
        "{%0,%1,%2,%3},{%4,%5,%6,%7},{%8,%9},{%0,%1,%2,%3};"
        : "+f"(c[0]), "+f"(c[1]), "+f"(c[2]), "+f"(c[3])
        : "r"(a[0]), "r"(a[1]), "r"(a[2]), "r"(a[3]), "r"(b0), "r"(b1));
}

// ---------------- prep: norms + bf16 conversion ----------------
__device__ __forceinline__ void prep_row_impl(const float* __restrict__ src,
                                              __nv_bfloat16* __restrict__ dst,
                                              float* __restrict__ inv, bool norm_dst) {
    int row = blockIdx.x;
    const float4* s4 = reinterpret_cast<const float4*>(src + (size_t)row * DIM);
    float4 v = s4[threadIdx.x];
    float ss = v.x * v.x + v.y * v.y + v.z * v.z + v.w * v.w;
    #pragma unroll
    for (int o = 16; o; o >>= 1) ss += __shfl_down_sync(0xffffffffu, ss, o);
    __shared__ float warpsum[8];
    __shared__ float s_inv;
    if ((threadIdx.x & 31) == 0) warpsum[threadIdx.x >> 5] = ss;
    __syncthreads();
    if (threadIdx.x == 0) {
        float t = 0.f;
        #pragma unroll
        for (int i = 0; i < 8; i++) t += warpsum[i];
        float iv = 1.0f / fmaxf(sqrtf(t), 1e-12f);
        inv[row] = iv;
        s_inv = iv;
    }
    __syncthreads();
    float sc = norm_dst ? s_inv : 1.0f;
    __nv_bfloat16* d = dst + (size_t)row * DIM + threadIdx.x * 4;
    d[0] = __float2bfloat16(v.x * sc);
    d[1] = __float2bfloat16(v.y * sc);
    d[2] = __float2bfloat16(v.z * sc);
    d[3] = __float2bfloat16(v.w * sc);
}

__global__ void prep_mem_kernel(const float* __restrict__ src) {
    prep_row_impl(src, g_memb, g_minv, true);   // fold inv-norm into bf16 memory
}
__global__ void prep_x_kernel(const float* __restrict__ src) {
    prep_row_impl(src, g_xb, g_xinv, false);    // row scale irrelevant for ranking
}

// ---------------- coarse GEMM (bf16 HMMA) + per-tile top-8 ----------------
__global__ __launch_bounds__(256) void gemm_topk_kernel() {
    extern __shared__ char smem[];
    const int tid = threadIdx.x;
    const int bm = blockIdx.x;   // 0..31  (fast dim -> consecutive CTAs share B tile in L2)
    const int bn = blockIdx.y;   // 0..511
    const uint32_t smem_u = (uint32_t)__cvta_generic_to_shared(smem);

    const int r0 = tid >> 2;     // 0..63
    const int ch = tid & 3;      // 16B chunk 0..3
    const __nv_bfloat16* gA0 = g_xb   + ((size_t)(bm * BM + r0)      * DIM + ch * 8);
    const __nv_bfloat16* gA1 = g_xb   + ((size_t)(bm * BM + r0 + 64) * DIM + ch * 8);
    const __nv_bfloat16* gB0 = g_memb + ((size_t)(bn * BN + r0)      * DIM + ch * 8);
    const __nv_bfloat16* gB1 = g_memb + ((size_t)(bn * BN + r0 + 64) * DIM + ch * 8);

    const uint32_t sa0 = (r0 * SROW + ch * 8) * 2;
    const uint32_t sa1 = ((r0 + 64) * SROW + ch * 8) * 2;

    float acc[4][4][4];
    #pragma unroll
    for (int i = 0; i < 4; i++)
        #pragma unroll
        for (int j = 0; j < 4; j++)
            #pragma unroll
            for (int q = 0; q < 4; q++) acc[i][j][q] = 0.f;

    const int lane = tid & 31;
    const int wm = ((tid >> 5) & 1) * 64;  // warp M offset (2 warps on M)
    const int wn = (tid >> 6) * 32;        // warp N offset (4 warps on N)

    // prologue: load stage 0
    {
        uint32_t base = smem_u;
        cp16(base + sa0, gA0);
        cp16(base + sa1, gA1);
        cp16(base + BM * SROW * 2 + sa0, gB0);
        cp16(base + BM * SROW * 2 + sa1, gB1);
        cp_commit();
    }

    const int NK = DIM / BK;  // 32
    for (int it = 0; it < NK; ++it) {
        if (it + 1 < NK) {
            uint32_t base = smem_u + ((it + 1) & 1) * STAGE_BYTES;
            size_t koff = (size_t)(it + 1) * BK;
            cp16(base + sa0, gA0 + koff);
            cp16(base + sa1, gA1 + koff);
            cp16(base + BM * SROW * 2 + sa0, gB0 + koff);
            cp16(base + BM * SROW * 2 + sa1, gB1 + koff);
            cp_commit();
            asm volatile("cp.async.wait_group 1;");
        } else {
            asm volatile("cp.async.wait_group 0;");
        }
        __syncthreads();

        uint32_t abase = smem_u + (it & 1) * STAGE_BYTES;
        uint32_t bbase = abase + BM * SROW * 2;
        #pragma unroll
        for (int kb = 0; kb < 2; ++kb) {
            uint32_t a[4][4];
            #pragma unroll
            for (int mi = 0; mi < 4; ++mi) {
                uint32_t ad = abase +
                    ((wm + mi * 16 + (lane & 15)) * SROW + kb * 16 + (lane >> 4) * 8) * 2;
                ldsm4(a[mi], ad);
            }
            uint32_t bfr[4][2];
            #pragma unroll
            for (int bp = 0; bp < 2; ++bp) {
                int mat = lane >> 3;
                uint32_t bd = bbase +
                    ((wn + bp * 16 + (mat >> 1) * 8 + (lane & 7)) * SROW +
                     kb * 16 + (mat & 1) * 8) * 2;
                uint32_t r[4];
                ldsm4(r, bd);
                bfr[bp * 2 + 0][0] = r[0]; bfr[bp * 2 + 0][1] = r[1];
                bfr[bp * 2 + 1][0] = r[2]; bfr[bp * 2 + 1][1] = r[3];
            }
            #pragma unroll
            for (int mi = 0; mi < 4; ++mi)
                #pragma unroll
                for (int ni = 0; ni < 4; ++ni)
                    mma16816(acc[mi][ni], a[mi], bfr[ni][0], bfr[ni][1]);
        }
        __syncthreads();
    }

    // epilogue: dump sims to smem, per-row top-8
    float* Cs = reinterpret_cast<float*>(smem);
    #pragma unroll
    for (int mi = 0; mi < 4; ++mi) {
        #pragma unroll
        for (int ni = 0; ni < 4; ++ni) {
            int rb = wm + mi * 16 + (lane >> 2);
            int cb = wn + ni * 8 + (lane & 3) * 2;
            Cs[rb * CS_STRIDE + cb]             = acc[mi][ni][0];
            Cs[rb * CS_STRIDE + cb + 1]         = acc[mi][ni][1];
            Cs[(rb + 8) * CS_STRIDE + cb]       = acc[mi][ni][2];
            Cs[(rb + 8) * CS_STRIDE + cb + 1]   = acc[mi][ni][3];
        }
    }
    __syncthreads();

    if (tid < BM) {
        const float* rowp = Cs + tid * CS_STRIDE;
        float tv[CAND_PER_TILE];
        int   tc[CAND_PER_TILE];
        #pragma unroll
        for (int i = 0; i < CAND_PER_TILE; i++) { tv[i] = -1e30f; tc[i] = 0; }
        for (int c = 0; c < BN; ++c) {
            float v = rowp[c];
            if (v > tv[CAND_PER_TILE - 1]) {
                int p = CAND_PER_TILE - 1;
                while (p > 0 && v > tv[p - 1]) { tv[p] = tv[p - 1]; tc[p] = tc[p - 1]; --p; }
                tv[p] = v; tc[p] = c;
            }
        }
        size_t base = ((size_t)(bm * BM + tid) * NTILES + bn) * CAND_PER_TILE;
        #pragma unroll
        for (int i = 0; i < CAND_PER_TILE; i++) {
            g_cv[base + i] = tv[i];
            g_ci[base + i] = bn * BN + tc[i];
        }
    }
}

// ---------------- phase 2: exact rescore, top-5, softmax, weighted gather ----------------
__global__ __launch_bounds__(256) void rescore_out_kernel(const float* __restrict__ x,
                                                          const float* __restrict__ mem,
                                                          float* __restrict__ out) {
    const int row = blockIdx.x;
    const int tid = threadIdx.x, lane = tid & 31, warp = tid >> 5;
    __shared__ float sv[CAND_PER_ROW];
    __shared__ float wv[8];
    __shared__ int   wp[8];
    __shared__ int   cpos[RESCORE];
    __shared__ float ev[RESCORE];
    __shared__ int   em[RESCORE];
    __shared__ float wgt[TOPK];
    __shared__ int   sidx[TOPK];

    const float4* cv4 = reinterpret_cast<const float4*>(g_cv + (size_t)row * CAND_PER_ROW);
    float4* sv4 = reinterpret_cast<float4*>(sv);
    for (int j = tid; j < CAND_PER_ROW / 4; j += 256) sv4[j] = cv4[j];
    __syncthreads();

    // approx top-16 by coarse score
    for (int i = 0; i < RESCORE; ++i) {
        float best = -1e30f; int bp = -1;
        for (int j = tid; j < CAND_PER_ROW; j += 256) {
            float v = sv[j];
            if (v > best) { best = v; bp = j; }
        }
        #pragma unroll
        for (int o = 16; o; o >>= 1) {
            float ov = __shfl_down_sync(0xffffffffu, best, o);
            int   op = __shfl_down_sync(0xffffffffu, bp, o);
            if (ov > best) { best = ov; bp = op; }
        }
        if (lane == 0) { wv[warp] = best; wp[warp] = bp; }
        __syncthreads();
        if (tid == 0) {
            float bb = wv[0]; int pp = wp[0];
            #pragma unroll
            for (int w = 1; w < 8; w++) if (wv[w] > bb) { bb = wv[w]; pp = wp[w]; }
            cpos[i] = pp;
            sv[pp] = -1e30f;
        }
        __syncthreads();
    }

    // exact fp32 rescore of 16 candidates (2 per warp)
    const float4* xr = reinterpret_cast<const float4*>(x + (size_t)row * DIM);
    for (int i = warp; i < RESCORE; i += 8) {
        int mi = g_ci[(size_t)row * CAND_PER_ROW + cpos[i]];
        const float4* mr = reinterpret_cast<const float4*>(mem + (size_t)mi * DIM);
        float s = 0.f;
        for (int j = lane; j < DIM / 4; j += 32) {
            float4 a = xr[j], b = mr[j];
            s += a.x * b.x + a.y * b.y + a.z * b.z + a.w * b.w;
        }
        #pragma unroll
        for (int o = 16; o; o >>= 1) s += __shfl_down_sync(0xffffffffu, s, o);
        if (lane == 0) { ev[i] = s * g_minv[mi] * g_xinv[row]; em[i] = mi; }
    }
    __syncthreads();

    if (tid == 0) {
        bool used[RESCORE];
        #pragma unroll
        for (int i = 0; i < RESCORE; i++) used[i] = false;
        float tv[TOPK]; int ti[TOPK];
        #pragma unroll
        for (int r = 0; r < TOPK; ++r) {
            float bb = -1e30f; int pp = 0;
            for (int i = 0; i < RESCORE; i++)
                if (!used[i] && ev[i] > bb) { bb = ev[i]; pp = i; }
            used[pp] = true; tv[r] = bb; ti[r] = pp;
        }
        float mx = tv[0];
        float e[TOPK], se = 0.f;
        #pragma unroll
        for (int i = 0; i < TOPK; i++) { e[i] = expf(tv[i] - mx); se += e[i]; }
        #pragma unroll
        for (int i = 0; i < TOPK; i++) { wgt[i] = e[i] / se; sidx[i] = em[ti[i]]; }
    }
    __syncthreads();

    // weighted gather of raw memory rows
    float4 accv = make_float4(0.f, 0.f, 0.f, 0.f);
    #pragma unroll
    for (int i = 0; i < TOPK; i++) {
        const float4* mr = reinterpret_cast<const float4*>(mem + (size_t)sidx[i] * DIM);
        float4 m = mr[tid];
        float w = wgt[i];
        accv.x += w * m.x; accv.y += w * m.y; accv.z += w * m.z; accv.w += w * m.w;
    }
    reinterpret_cast<float4*>(out + (size_t)row * DIM)[tid] = accv;
}

// ---------------- launch ----------------
extern "C" void kernel_launch(void* const* d_in, const int* in_sizes, int n_in,
                              void* d_out, int out_size) {
    const float* x   = (const float*)d_in[0];
    const float* mem = (const float*)d_in[1];
    float* out = (float*)d_out;

    cudaFuncSetAttribute(gemm_topk_kernel,
                         cudaFuncAttributeMaxDynamicSharedMemorySize, SMEM_BYTES);

    prep_mem_kernel<<<C_ROWS, 256>>>(mem);
    prep_x_kernel<<<B_ROWS, 256>>>(x);
    gemm_topk_kernel<<<dim3(B_ROWS / BM, NTILES), 256, SMEM_BYTES>>>();
    rescore_out_kernel<<<B_ROWS, 256>>>(x, mem, out);
}